// round 11
// baseline (speedup 1.0000x reference)
#include <cuda_runtime.h>
#include <math.h>

#define VOCAB 32000
#define Q4    8000     // float4 per row
#define KNN   32
#define NT    256
#define LOG2E 1.4426950408889634f

__device__ float g_lscale[2048];   // per-row log2(scale) scratch (static device global)

__device__ __forceinline__ float warp_max(float v) {
    #pragma unroll
    for (int o = 16; o > 0; o >>= 1) v = fmaxf(v, __shfl_xor_sync(0xFFFFFFFFu, v, o));
    return v;
}
__device__ __forceinline__ float warp_sum(float v) {
    #pragma unroll
    for (int o = 16; o > 0; o >>= 1) v += __shfl_xor_sync(0xFFFFFFFFu, v, o);
    return v;
}

__device__ __forceinline__ float4 ldlu4(const float4* p) {
    float4 r;
    asm volatile("ld.global.lu.v4.f32 {%0,%1,%2,%3}, [%4];"
                 : "=f"(r.x), "=f"(r.y), "=f"(r.z), "=f"(r.w) : "l"(p));
    return r;
}
__device__ __forceinline__ void stcs4(float4* p, float4 v) {
    asm volatile("st.global.cs.v4.f32 [%0], {%1,%2,%3,%4};"
                 :: "l"(p), "f"(v.x), "f"(v.y), "f"(v.z), "f"(v.w) : "memory");
}

// ---------- Kernel A: per-row exp-sum (pure DRAM read stream) ----------
__global__ __launch_bounds__(NT, 8)
void sum_kernel(const float* __restrict__ logits,
                const int*   __restrict__ prev_words,
                const float* __restrict__ optor_lamda,
                const float* __restrict__ const_lamda)
{
    __shared__ float red[8];
    const int r    = blockIdx.x;
    const int tid  = threadIdx.x;
    const int wid  = tid >> 5;
    const int lane = tid & 31;

    const float4* __restrict__ l4 = (const float4*)(logits + (size_t)r * VOCAB);

    float s = 0.0f;
    #pragma unroll 4
    for (int i = tid; i < Q4; i += NT) {
        float4 x = l4[i];
        s += exp2f(x.x * LOG2E) + exp2f(x.y * LOG2E)
           + exp2f(x.z * LOG2E) + exp2f(x.w * LOG2E);
    }
    s = warp_sum(s);
    if (lane == 0) red[wid] = s;
    __syncthreads();
    if (tid < 32) {
        float v = (lane < 8) ? red[lane] : 0.0f;
        v = warp_sum(v);
        if (lane == 0) {
            const int p = prev_words[r];
            const bool om = (p <= 88) | ((p >= 91) & (p <= 291));
            const bool cm = (p == 89) | (p == 90) | (p >= 292);
            const float base = (om ? (1.0f - optor_lamda[0]) : 0.0f)
                             + (cm ? (1.0f - const_lamda[0]) : 0.0f);
            g_lscale[r] = log2f(base / v);   // scale > 0 (masks exhaustive)
        }
    }
}

// ---------- Kernel B: scale + write (L2-hit reads, DRAM write stream) ----------
__global__ __launch_bounds__(NT, 8)
void scale_kernel(const float* __restrict__ logits,
                  const int*   __restrict__ optor_vals,
                  const float* __restrict__ optor_dists,
                  const int*   __restrict__ const_vals,
                  const float* __restrict__ const_dists,
                  const int*   __restrict__ prev_words,
                  const float* __restrict__ optor_lamda,
                  const float* __restrict__ const_lamda,
                  const float* __restrict__ optor_temp,
                  const float* __restrict__ const_temp,
                  float*       __restrict__ out,
                  int          rows)
{
    const int r    = rows - 1 - blockIdx.x;   // reverse order: hottest L2 rows first
    const int tid  = threadIdx.x;
    const int wid  = tid >> 5;
    const int lane = tid & 31;

    const float4* __restrict__ l4 = (const float4*)(logits + (size_t)r * VOCAB);
    float4* __restrict__ o4 = (float4*)(out + (size_t)r * VOCAB);
    float*  __restrict__ orow = out + (size_t)r * VOCAB;

    const float lscale = g_lscale[r];

    #pragma unroll 4
    for (int i = tid; i < Q4; i += NT) {
        float4 x = ldlu4(&l4[i]);             // L2 hit (retained from kernel A), last-use
        float4 y;
        y.x = exp2f(fmaf(x.x, LOG2E, lscale));
        y.y = exp2f(fmaf(x.y, LOG2E, lscale));
        y.z = exp2f(fmaf(x.z, LOG2E, lscale));
        y.w = exp2f(fmaf(x.w, LOG2E, lscale));
        stcs4(&o4[i], y);
    }
    __syncthreads();   // row's base stores issued before scatter atomics

    // ---- Scatter: warp 0 = optor, warp 1 = const ----
    if (wid == 0) {
        const int p = prev_words[r];
        const bool om = (p <= 88) | ((p >= 91) & (p <= 291));
        const float t = optor_temp[0];
        const float d = optor_dists[(size_t)r * KNN + lane];
        const float x = -d / t;
        const float mm = warp_max(x);
        const float e  = __expf(x - mm);
        const float ss = warp_sum(e);
        if (om) atomicAdd(&orow[optor_vals[(size_t)r * KNN + lane]],
                          optor_lamda[0] * e / ss);
    } else if (wid == 1) {
        const int p = prev_words[r];
        const bool cm = (p == 89) | (p == 90) | (p >= 292);
        const float t = const_temp[0];
        const float d = const_dists[(size_t)r * KNN + lane];
        const float x = -d / t;
        const float mm = warp_max(x);
        const float e  = __expf(x - mm);
        const float ss = warp_sum(e);
        if (cm) atomicAdd(&orow[const_vals[(size_t)r * KNN + lane]],
                          const_lamda[0] * e / ss);
    }
}

extern "C" void kernel_launch(void* const* d_in, const int* in_sizes, int n_in,
                              void* d_out, int out_size)
{
    const float* logits      = (const float*)d_in[0];
    const int*   optor_vals  = (const int*)  d_in[1];
    const float* optor_dists = (const float*)d_in[2];
    const int*   const_vals  = (const int*)  d_in[3];
    const float* const_dists = (const float*)d_in[4];
    const int*   prev_words  = (const int*)  d_in[5];
    const float* optor_lamda = (const float*)d_in[6];
    const float* const_lamda = (const float*)d_in[7];
    const float* optor_temp  = (const float*)d_in[8];
    const float* const_temp  = (const float*)d_in[9];
    float* out = (float*)d_out;

    const int rows = in_sizes[5];                 // B*S = 1024

    sum_kernel<<<rows, NT>>>(logits, prev_words, optor_lamda, const_lamda);
    scale_kernel<<<rows, NT>>>(
        logits, optor_vals, optor_dists, const_vals, const_dists,
        prev_words, optor_lamda, const_lamda, optor_temp, const_temp, out, rows);
}